// round 5
// baseline (speedup 1.0000x reference)
#include <cuda_runtime.h>
#include <cuda_bf16.h>

#define B_     32
#define S_     2048
#define D_     1536
#define G_     150
#define K_     9
#define R_     32
#define MAXT   150
#define LW     48     // 1536-bit removal bitmap -> 48 x u32
#define PPB    5      // positions per block
#define CHUNKS 30     // PPB * CHUNKS == MAXT
#define NT     128    // threads per block
#define SEGS   3      // 128 threads * 3 float4 = 384 float4 = 1536 floats

// ---------------------------------------------------------------------------
// One block per (chunk of 5 output positions, sample). 128 threads.
// Prep (removal bitmap, valid counts, right-aligned dest scan) replicated per
// block (~350 cyc), then 45 gather-row pointers staged in smem and the main
// loop is pure LDG/FADD/STG. Small blocks => fine-grained SM load balance:
// 960 blocks, 8/SM slots, single wave, max/avg = 7/6.49.
// ---------------------------------------------------------------------------
__global__ __launch_bounds__(NT, 8)
void fused_pool_kernel(const float* __restrict__ h,
                       const int* __restrict__ patch_range,
                       const int* __restrict__ patch_idx,
                       const int* __restrict__ remove_idx,
                       float* __restrict__ out,
                       float* __restrict__ attn_out)
{
    const int c = blockIdx.x;   // position chunk 0..29
    const int b = blockIdx.y;   // sample
    const int t = threadIdx.x;  // 0..127

    __shared__ unsigned s_bm[LW];          // removal bitmap over [0,1536)
    __shared__ int s_cnt[G_];              // per-group valid count
    __shared__ unsigned s_kw[5];           // keep bitmask words (groups 0..159)
    __shared__ int s_wp[5];                // popc of each keep word
    __shared__ int s_p2g[MAXT];            // dest position -> group
    __shared__ const float4* s_rows[PPB * K_];
    __shared__ float s_inv[PPB];

    // ---- prep: removal bitmap ----
    if (t < LW)        s_bm[t] = 0u;
    if (t < MAXT)      s_p2g[t] = -1;
    if (t >= MAXT - NT && t < MAXT) {}     // (rest of p2g init below)
    if (t < MAXT - NT) s_p2g[NT + t] = -1; // covers 128..149
    __syncthreads();
    if (t < R_) {
        int v = remove_idx[b * R_ + t];
        if ((unsigned)v < 1536u) atomicOr(&s_bm[v >> 5], 1u << (v & 31));
    }
    __syncthreads();

    // ---- prep: per-group valid counts (two passes: groups t and t+128) ----
    int keep0 = 0, keep1 = 0;
#pragma unroll
    for (int pass = 0; pass < 2; pass++) {
        int g = t + pass * NT;
        if (g < G_) {
            const int* gi = patch_idx + (b * G_ + g) * K_;
            int cnt = 0;
#pragma unroll
            for (int k = 0; k < K_; k++) {
                int v = gi[k];
                bool valid = (v != -1);
                if (valid && (unsigned)v < 1536u)
                    valid = ((s_bm[v >> 5] >> (v & 31)) & 1u) == 0u;
                cnt += valid ? 1 : 0;
            }
            s_cnt[g] = cnt;
            if (pass == 0) keep0 = (cnt > 0); else keep1 = (cnt > 0);
        }
    }
    // keep bitmask: words 0-3 from warps 0-3 (groups 0-127), word 4 from warp 0
    unsigned m0 = __ballot_sync(0xFFFFFFFFu, keep0);
    unsigned m1 = __ballot_sync(0xFFFFFFFFu, keep1);
    const int w = t >> 5, lane = t & 31;
    if (lane == 0) s_kw[w] = m0;
    if (t == 0)    s_kw[4] = m1;           // only lanes 0..21 can be set (g<150)
    __syncthreads();
    if (t < 5) s_wp[t] = __popc(s_kw[t]);
    __syncthreads();

    // ---- prep: scatter right-aligned dest positions ----
    const int nk = s_wp[0] + s_wp[1] + s_wp[2] + s_wp[3] + s_wp[4];
#pragma unroll
    for (int pass = 0; pass < 2; pass++) {
        int g = t + pass * NT;
        int kp = (pass == 0) ? keep0 : keep1;
        if (g < G_ && kp) {
            int wi = g >> 5;
            int before = __popc(s_kw[wi] & ((1u << (g & 31)) - 1u));
            for (int w2 = 0; w2 < wi; w2++) before += s_wp[w2];
            s_p2g[MAXT - nk + before] = g;
        }
    }
    __syncthreads();

    // ---- setup: stage row pointers + scales for this block's 5 positions ----
    if (t < PPB) {
        int p = c * PPB + t;
        int g = s_p2g[p];
        s_inv[t] = (g >= 0) ? 1.0f / (float)max(s_cnt[g], 1) : 0.0f;
        attn_out[b * MAXT + p] = (g >= 0) ? 1.0f : 0.0f;
    }
    if (t < PPB * K_) {
        int i = t / K_, k = t - i * K_;
        int g = s_p2g[c * PPB + i];
        const float* base = h + (size_t)b * S_ * D_;
        int row = 0;                        // dummy (inv=0) for dropped positions
        if (g >= 0) {
            int start = patch_range[b * 2 + 0];
            int end   = patch_range[b * 2 + 1];
            int v = patch_idx[(b * G_ + g) * K_ + k];
            row = (v >= 0) ? (start + v) : (end + 1 + v);   // reference wrap
        }
        s_rows[t] = reinterpret_cast<const float4*>(base + (size_t)row * D_);
    }
    __syncthreads();

    // ---- main loop: pure gather/accumulate/store ----
    float4* obase = reinterpret_cast<float4*>(out + ((size_t)(b * MAXT) + c * PPB) * D_);
#pragma unroll 1
    for (int i = 0; i < PPB; i++) {
        const float inv = s_inv[i];
#pragma unroll 1
        for (int seg = 0; seg < SEGS; seg++) {
            const int col = seg * NT + t;   // float4 column 0..383
            float4 acc = make_float4(0.f, 0.f, 0.f, 0.f);
#pragma unroll
            for (int k = 0; k < K_; k++) {
                float4 v = s_rows[i * K_ + k][col];
                acc.x += v.x; acc.y += v.y; acc.z += v.z; acc.w += v.w;
            }
            acc.x *= inv; acc.y *= inv; acc.z *= inv; acc.w *= inv;
            obase[(size_t)i * (D_ / 4) + col] = acc;
        }
    }
}

extern "C" void kernel_launch(void* const* d_in, const int* in_sizes, int n_in,
                              void* d_out, int out_size)
{
    const float* hidden    = (const float*)d_in[0];  // [B,S,D] f32
    // d_in[1] attention_mask, d_in[2] image_grid_thw: unused by the math
    const int* patch_range = (const int*)d_in[3];    // [B,2]
    const int* patch_idx   = (const int*)d_in[4];    // [B,G,K]
    const int* remove_idx  = (const int*)d_in[5];    // [B,R]

    float* out      = (float*)d_out;                 // [B,MAXT,D]
    float* attn_out = out + (size_t)B_ * MAXT * D_;  // [B,MAXT]

    dim3 grid(CHUNKS, B_);
    fused_pool_kernel<<<grid, NT>>>(hidden, patch_range, patch_idx, remove_idx,
                                    out, attn_out);
}

// round 6
// speedup vs baseline: 1.0069x; 1.0069x over previous
#include <cuda_runtime.h>
#include <cuda_bf16.h>

#define B_     32
#define S_     2048
#define D_     1536
#define G_     150
#define K_     9
#define R_     32
#define MAXT   150
#define LW     48     // 1536-bit removal bitmap -> 48 x u32
#define NT     384
#define CHUNKS 18     // 6 chunks of 9 rows + 12 chunks of 8 rows = 150
#define MAXPPB 9

// ---------------------------------------------------------------------------
// One block per (row-chunk, sample): grid = 18 x 32 = 576 blocks, 384 thr,
// ~38 regs => 4 blocks/SM, single wave on 148 SMs (592 slots), max/avg
// per-SM load = 1.03. Prep (removal bitmap, counts, right-aligned scan) is
// replicated per block (~0.7us aggregate). Main loop: pure LDG.128 gather
// (MLP=9) + FADD + STG.128, no syncs.
// ---------------------------------------------------------------------------
__global__ __launch_bounds__(NT, 4)
void fused_pool_kernel(const float* __restrict__ h,
                       const int* __restrict__ patch_range,
                       const int* __restrict__ patch_idx,
                       const int* __restrict__ remove_idx,
                       float* __restrict__ out,
                       float* __restrict__ attn_out)
{
    const int c = blockIdx.x;   // chunk 0..17
    const int b = blockIdx.y;   // sample
    const int t = threadIdx.x;  // 0..383

    // chunk -> [r0, r0+n) rows of this sample
    const int n  = (c < 6) ? 9 : 8;
    const int r0 = (c < 6) ? c * 9 : 54 + (c - 6) * 8;

    __shared__ unsigned s_bm[LW];
    __shared__ int s_cnt[G_];
    __shared__ int s_p2g[MAXT];
    __shared__ int s_wsum[5];
    __shared__ const float4* s_rows[MAXPPB * K_];
    __shared__ float s_inv[MAXPPB];

    // ---- prep: removal bitmap ----
    if (t < LW)   s_bm[t] = 0u;
    if (t < MAXT) s_p2g[t] = -1;
    __syncthreads();
    if (t < R_) {
        int v = remove_idx[b * R_ + t];
        if ((unsigned)v < 1536u) atomicOr(&s_bm[v >> 5], 1u << (v & 31));
    }
    __syncthreads();

    // ---- prep: per-group valid counts ----
    int keep = 0;
    if (t < G_) {
        const int* gi = patch_idx + (b * G_ + t) * K_;
        int cnt = 0;
#pragma unroll
        for (int k = 0; k < K_; k++) {
            int v = gi[k];
            bool valid = (v != -1);
            if (valid && (unsigned)v < 1536u)
                valid = ((s_bm[v >> 5] >> (v & 31)) & 1u) == 0u;
            cnt += valid ? 1 : 0;
        }
        s_cnt[t] = cnt;
        keep = (cnt > 0) ? 1 : 0;
    }

    // ---- prep: ballot prefix scan -> right-aligned dest ----
    const unsigned bmask = __ballot_sync(0xFFFFFFFFu, keep);
    const int w = t >> 5, lane = t & 31;
    if (lane == 0 && w < 5) s_wsum[w] = __popc(bmask);
    __syncthreads();
    if (keep) {  // implies t < 150 => w <= 4
        int nk = s_wsum[0] + s_wsum[1] + s_wsum[2] + s_wsum[3] + s_wsum[4];
        int before = __popc(bmask & ((1u << lane) - 1u));
        for (int w2 = 0; w2 < w; w2++) before += s_wsum[w2];
        s_p2g[MAXT - nk + before] = t;
    }
    __syncthreads();

    // ---- setup: stage row pointers + scales for this block's rows ----
    if (t < n) {
        int p = r0 + t;
        int g = s_p2g[p];
        s_inv[t] = (g >= 0) ? 1.0f / (float)max(s_cnt[g], 1) : 0.0f;
        attn_out[b * MAXT + p] = (g >= 0) ? 1.0f : 0.0f;
    }
    if (t < n * K_) {
        int i = t / K_, k = t - i * K_;
        int g = s_p2g[r0 + i];
        const float* base = h + (size_t)b * S_ * D_;
        int row = 0;                         // dummy (inv=0) for dropped rows
        if (g >= 0) {
            int start = patch_range[b * 2 + 0];
            int end   = patch_range[b * 2 + 1];
            int v = patch_idx[(b * G_ + g) * K_ + k];
            row = (v >= 0) ? (start + v) : (end + 1 + v);   // reference wrap
        }
        s_rows[t] = reinterpret_cast<const float4*>(base + (size_t)row * D_);
    }
    __syncthreads();

    // ---- main loop: pure gather/accumulate/store, branchless ----
    float4* obase = reinterpret_cast<float4*>(out + ((size_t)(b * MAXT) + r0) * D_);
#pragma unroll 1
    for (int i = 0; i < n; i++) {
        const float inv = s_inv[i];
        float4 acc = make_float4(0.f, 0.f, 0.f, 0.f);
#pragma unroll
        for (int k = 0; k < K_; k++) {
            float4 v = s_rows[i * K_ + k][t];
            acc.x += v.x; acc.y += v.y; acc.z += v.z; acc.w += v.w;
        }
        acc.x *= inv; acc.y *= inv; acc.z *= inv; acc.w *= inv;
        obase[(size_t)i * (D_ / 4) + t] = acc;
    }
}

extern "C" void kernel_launch(void* const* d_in, const int* in_sizes, int n_in,
                              void* d_out, int out_size)
{
    const float* hidden    = (const float*)d_in[0];  // [B,S,D] f32
    // d_in[1] attention_mask, d_in[2] image_grid_thw: unused by the math
    const int* patch_range = (const int*)d_in[3];    // [B,2]
    const int* patch_idx   = (const int*)d_in[4];    // [B,G,K]
    const int* remove_idx  = (const int*)d_in[5];    // [B,R]

    float* out      = (float*)d_out;                 // [B,MAXT,D]
    float* attn_out = out + (size_t)B_ * MAXT * D_;  // [B,MAXT]

    dim3 grid(CHUNKS, B_);
    fused_pool_kernel<<<grid, NT>>>(hidden, patch_range, patch_idx, remove_idx,
                                    out, attn_out);
}

// round 9
// speedup vs baseline: 1.0148x; 1.0078x over previous
#include <cuda_runtime.h>
#include <cuda_bf16.h>
#include <cstdint>

#define B_     32
#define S_     2048
#define D_     1536
#define G_     150
#define K_     9
#define R_     32
#define MAXT   150
#define LW     48        // 1536-bit removal bitmap -> 48 x u32
#define NT     416       // 384 consumers + 1 producer warp
#define NCONS  384
#define PPB    10        // output rows per block
#define CHUNKS 15        // PPB * CHUNKS == MAXT
#define SLOTS  7         // smem ring depth (7 x 6KB = 42KB)
#define ROWB   6144      // bytes per hidden row (D_*4)
#define NJ     (PPB*K_)  // 90 gathered rows per block

__device__ __forceinline__ uint32_t smem_u32(const void* p) {
    uint32_t a;
    asm("{ .reg .u64 t; cvta.to.shared.u64 t, %1; cvt.u32.u64 %0, t; }" : "=r"(a) : "l"(p));
    return a;
}

// acquire wait (consumer side: generic LDS follows)
__device__ __forceinline__ void mbar_wait_acq(uint32_t mbar, uint32_t parity) {
    asm volatile(
        "{\n\t.reg .pred P;\n\t"
        "W%=:\n\t"
        "mbarrier.try_wait.parity.acquire.cta.shared::cta.b64 P, [%0], %1, 0x989680;\n\t"
        "@P bra.uni D%=;\n\t"
        "bra.uni W%=;\n\t"
        "D%=:\n\t}"
        :: "r"(mbar), "r"(parity) : "memory");
}

// relaxed wait (producer side: post-wait access is async-proxy TMA only)
__device__ __forceinline__ void mbar_wait_rlx(uint32_t mbar, uint32_t parity) {
    asm volatile(
        "{\n\t.reg .pred P;\n\t"
        "W%=:\n\t"
        "mbarrier.try_wait.parity.relaxed.cta.shared::cta.b64 P, [%0], %1, 0x989680;\n\t"
        "@P bra.uni D%=;\n\t"
        "bra.uni W%=;\n\t"
        "D%=:\n\t}"
        :: "r"(mbar), "r"(parity) : "memory");
}

// ---------------------------------------------------------------------------
// Warp-specialized gather-average. One block per (10-row chunk, sample).
// Producer thread streams 90 gathered rows (6KB each) through a 7-slot smem
// ring via cp.async.bulk; 384 consumer threads accumulate rows as they land
// and store averages. Load issue is decoupled from the consume dependency
// chain -> DRAM stays continuously fed.
// ---------------------------------------------------------------------------
__global__ __launch_bounds__(NT, 4)
void fused_pool_tma(const float* __restrict__ h,
                    const int* __restrict__ patch_range,
                    const int* __restrict__ patch_idx,
                    const int* __restrict__ remove_idx,
                    float* __restrict__ out,
                    float* __restrict__ attn_out)
{
    const int c = blockIdx.x;   // chunk 0..14
    const int b = blockIdx.y;   // sample
    const int t = threadIdx.x;  // 0..415

    __shared__ __align__(128) char s_slots[SLOTS * ROWB];      // 43008 B
    __shared__ __align__(8) unsigned long long s_full[SLOTS];
    __shared__ __align__(8) unsigned long long s_empty[SLOTS];
    __shared__ const float* s_gptr[NJ];
    __shared__ float s_inv[PPB];
    __shared__ unsigned s_bm[LW];
    __shared__ int s_cnt[G_];
    __shared__ int s_p2g[MAXT];
    __shared__ int s_wsum[5];

    const uint32_t slot0   = smem_u32(s_slots);
    const uint32_t fullb0  = smem_u32(s_full);
    const uint32_t emptyb0 = smem_u32(s_empty);

    // ---- init: mbarriers + removal bitmap + p2g ----
    if (t == 0) {
        for (int s = 0; s < SLOTS; s++) {
            asm volatile("mbarrier.init.shared.b64 [%0], %1;" :: "r"(fullb0 + 8u*s),  "r"(1u)            : "memory");
            asm volatile("mbarrier.init.shared.b64 [%0], %1;" :: "r"(emptyb0 + 8u*s), "r"((unsigned)NCONS) : "memory");
        }
        asm volatile("fence.proxy.async.shared::cta;" ::: "memory");
    }
    if (t < LW)   s_bm[t] = 0u;
    if (t < MAXT) s_p2g[t] = -1;
    __syncthreads();
    if (t < R_) {
        int v = remove_idx[b * R_ + t];
        if ((unsigned)v < 1536u) atomicOr(&s_bm[v >> 5], 1u << (v & 31));
    }
    __syncthreads();

    // ---- prep: per-group valid counts (groups live in threads 0..149) ----
    int keep = 0;
    if (t < G_) {
        const int* gi = patch_idx + (b * G_ + t) * K_;
        int cnt = 0;
#pragma unroll
        for (int k = 0; k < K_; k++) {
            int v = gi[k];
            bool valid = (v != -1);
            if (valid && (unsigned)v < 1536u)
                valid = ((s_bm[v >> 5] >> (v & 31)) & 1u) == 0u;
            cnt += valid ? 1 : 0;
        }
        s_cnt[t] = cnt;
        keep = (cnt > 0) ? 1 : 0;
    }
    const unsigned bmask = __ballot_sync(0xFFFFFFFFu, keep);
    const int w = t >> 5, lane = t & 31;
    if (lane == 0 && w < 5) s_wsum[w] = __popc(bmask);
    __syncthreads();
    if (keep) {  // implies t < 150 => w <= 4
        int nk = s_wsum[0] + s_wsum[1] + s_wsum[2] + s_wsum[3] + s_wsum[4];
        int before = __popc(bmask & ((1u << lane) - 1u));
        for (int w2 = 0; w2 < w; w2++) before += s_wsum[w2];
        s_p2g[MAXT - nk + before] = t;
    }
    __syncthreads();

    // ---- setup: stage gather pointers + scales ----
    if (t < PPB) {
        int p = c * PPB + t;
        int g = s_p2g[p];
        s_inv[t] = (g >= 0) ? 1.0f / (float)max(s_cnt[g], 1) : 0.0f;
        attn_out[b * MAXT + p] = (g >= 0) ? 1.0f : 0.0f;
    }
    if (t < NJ) {
        int i = t / K_, k = t - i * K_;
        int g = s_p2g[c * PPB + i];
        int row = 0;                         // dummy (inv=0) for dropped rows
        if (g >= 0) {
            int start = patch_range[b * 2 + 0];
            int end   = patch_range[b * 2 + 1];
            int v = patch_idx[(b * G_ + g) * K_ + k];
            row = (v >= 0) ? (start + v) : (end + 1 + v);   // reference wrap
        }
        s_gptr[t] = h + ((size_t)b * S_ + row) * (size_t)D_;
    }
    __syncthreads();

    if (t >= NCONS) {
        // ================= producer (single thread of warp 12) =============
        if (t == NCONS) {
#pragma unroll 1
            for (int j = 0; j < NJ; j++) {
                int s = j % SLOTS, u = j / SLOTS;
                uint32_t fb = fullb0 + 8u * s;
                uint32_t eb = emptyb0 + 8u * s;
                if (u > 0) mbar_wait_rlx(eb, (unsigned)((u - 1) & 1));
                asm volatile("mbarrier.arrive.expect_tx.shared.b64 _, [%0], %1;"
                             :: "r"(fb), "r"((unsigned)ROWB) : "memory");
                asm volatile(
                    "cp.async.bulk.shared::cta.global.mbarrier::complete_tx::bytes [%0], [%1], %2, [%3];"
                    :: "r"(slot0 + (unsigned)(s * ROWB)), "l"(s_gptr[j]),
                       "r"((unsigned)ROWB), "r"(fb) : "memory");
            }
        }
    } else {
        // ================= consumers (threads 0..383) ======================
        float4* obase = reinterpret_cast<float4*>(out + ((size_t)(b * MAXT) + c * PPB) * D_);
#pragma unroll 1
        for (int i = 0; i < PPB; i++) {
            float4 acc = make_float4(0.f, 0.f, 0.f, 0.f);
#pragma unroll 1
            for (int k = 0; k < K_; k++) {
                int j = i * K_ + k;
                int s = j % SLOTS, u = j / SLOTS;
                mbar_wait_acq(fullb0 + 8u * s, (unsigned)(u & 1));
                float4 v = reinterpret_cast<const float4*>(s_slots + s * ROWB)[t];
                acc.x += v.x; acc.y += v.y; acc.z += v.z; acc.w += v.w;
                asm volatile("mbarrier.arrive.shared.b64 _, [%0];"
                             :: "r"(emptyb0 + 8u * s) : "memory");
            }
            const float inv = s_inv[i];
            acc.x *= inv; acc.y *= inv; acc.z *= inv; acc.w *= inv;
            obase[(size_t)i * (D_ / 4) + t] = acc;
        }
    }
}

extern "C" void kernel_launch(void* const* d_in, const int* in_sizes, int n_in,
                              void* d_out, int out_size)
{
    const float* hidden    = (const float*)d_in[0];  // [B,S,D] f32
    // d_in[1] attention_mask, d_in[2] image_grid_thw: unused by the math
    const int* patch_range = (const int*)d_in[3];    // [B,2]
    const int* patch_idx   = (const int*)d_in[4];    // [B,G,K]
    const int* remove_idx  = (const int*)d_in[5];    // [B,R]

    float* out      = (float*)d_out;                 // [B,MAXT,D]
    float* attn_out = out + (size_t)B_ * MAXT * D_;  // [B,MAXT]

    dim3 grid(CHUNKS, B_);
    fused_pool_tma<<<grid, NT>>>(hidden, patch_range, patch_idx, remove_idx,
                                 out, attn_out);
}

// round 10
// speedup vs baseline: 1.0733x; 1.0576x over previous
#include <cuda_runtime.h>
#include <cuda_bf16.h>
#include <cstdint>

#define B_     32
#define S_     2048
#define D_     1536
#define G_     150
#define K_     9
#define R_     32
#define MAXT   150
#define LW     48
#define NT     416        // 384 consumers + 1 producer warp
#define NCONS  384
#define PPB    10         // groups per block
#define CHUNKS 15
#define ROWB   6144       // bytes per hidden row
#define TRIOR  3          // rows per ring slot
#define TRIOB  (TRIOR*ROWB)
#define SLOTS  2          // ring depth (2 x 18KB)
#define NJ     (PPB*K_)   // 90 rows per block
#define NTRIOS (NJ/TRIOR) // 30

__device__ __forceinline__ uint32_t smem_u32(const void* p) {
    uint32_t a;
    asm("{ .reg .u64 t; cvta.to.shared.u64 t, %1; cvt.u32.u64 %0, t; }" : "=r"(a) : "l"(p));
    return a;
}
__device__ __forceinline__ void mbar_wait_acq(uint32_t mbar, uint32_t parity) {
    asm volatile(
        "{\n\t.reg .pred P;\n\tW%=:\n\t"
        "mbarrier.try_wait.parity.acquire.cta.shared::cta.b64 P, [%0], %1, 0x989680;\n\t"
        "@P bra.uni D%=;\n\tbra.uni W%=;\n\tD%=:\n\t}"
        :: "r"(mbar), "r"(parity) : "memory");
}
__device__ __forceinline__ void mbar_wait_rlx(uint32_t mbar, uint32_t parity) {
    asm volatile(
        "{\n\t.reg .pred P;\n\tW%=:\n\t"
        "mbarrier.try_wait.parity.relaxed.cta.shared::cta.b64 P, [%0], %1, 0x989680;\n\t"
        "@P bra.uni D%=;\n\tbra.uni W%=;\n\tD%=:\n\t}"
        :: "r"(mbar), "r"(parity) : "memory");
}
#define BAR(id, n) asm volatile("bar.sync %0, %1;" :: "r"(id), "r"(n) : "memory")

// ---------------------------------------------------------------------------
// Group-centric warp-specialized gather-average.
// Block owns groups [10c, 10c+10). Gather addresses depend ONLY on patch_idx/
// patch_range, so the producer warp starts streaming immediately; consumers
// run prep (bitmap/counts/keep-scan -> dest permutation + 1/cnt) underneath
// the in-flight TMA loads. Ring: 2 slots x 3 rows; per-warp empty arrives.
// ---------------------------------------------------------------------------
__global__ __launch_bounds__(NT, 4)
void fused_pool_gc(const float* __restrict__ h,
                   const int* __restrict__ patch_range,
                   const int* __restrict__ patch_idx,
                   const int* __restrict__ remove_idx,
                   float* __restrict__ out,
                   float* __restrict__ attn_out)
{
    const int c = blockIdx.x;         // group chunk 0..14
    const int b = blockIdx.y;         // sample
    const int t = threadIdx.x;        // 0..415
    const int g0 = c * PPB;

    __shared__ __align__(128) char s_slots[SLOTS * TRIOB];   // 36864 B
    __shared__ __align__(8) unsigned long long s_full[SLOTS];
    __shared__ __align__(8) unsigned long long s_empty[SLOTS];
    __shared__ const float* s_gptr[NJ];
    __shared__ float s_inv[PPB];
    __shared__ int s_dest[PPB];
    __shared__ unsigned s_bm[LW];
    __shared__ int s_cnt[G_];
    __shared__ unsigned s_kw[5];
    __shared__ int s_wp[5];

    const uint32_t slot0   = smem_u32(s_slots);
    const uint32_t fullb0  = smem_u32(s_full);
    const uint32_t emptyb0 = smem_u32(s_empty);

    if (t == 0) {
#pragma unroll
        for (int s = 0; s < SLOTS; s++) {
            asm volatile("mbarrier.init.shared.b64 [%0], %1;" :: "r"(fullb0 + 8u*s),  "r"(1u)  : "memory");
            asm volatile("mbarrier.init.shared.b64 [%0], %1;" :: "r"(emptyb0 + 8u*s), "r"(12u) : "memory");
        }
        asm volatile("fence.proxy.async.shared::cta;" ::: "memory");
    }

    if (t >= NCONS) {
        // ================= producer warp ===================================
        const int q = t - NCONS;
        const int start = patch_range[b * 2 + 0];
        const int end   = patch_range[b * 2 + 1];
#pragma unroll
        for (int r = 0; r < 3; r++) {
            int j = q + r * 32;
            if (j < NJ) {
                int g = g0 + j / K_, k = j % K_;
                int v = patch_idx[(b * G_ + g) * K_ + k];
                int row = (v >= 0) ? (start + v) : (end + 1 + v);   // ref wrap
                s_gptr[j] = h + ((size_t)b * S_ + row) * (size_t)D_;
            }
        }
        __syncwarp();
        BAR(0, NT);                    // mbarrier init + staging handshake
        if (q == 0) {
#pragma unroll 1
            for (int tr = 0; tr < NTRIOS; tr++) {
                int s = tr & 1, u = tr >> 1;
                uint32_t fb = fullb0 + 8u * s;
                if (u > 0) mbar_wait_rlx(emptyb0 + 8u * s, (unsigned)((u - 1) & 1));
                asm volatile("mbarrier.arrive.expect_tx.shared.b64 _, [%0], %1;"
                             :: "r"(fb), "r"((unsigned)TRIOB) : "memory");
#pragma unroll
                for (int r = 0; r < TRIOR; r++) {
                    asm volatile(
                        "cp.async.bulk.shared::cta.global.mbarrier::complete_tx::bytes [%0], [%1], %2, [%3];"
                        :: "r"(slot0 + (unsigned)(s * TRIOB + r * ROWB)),
                           "l"(s_gptr[tr * TRIOR + r]), "r"((unsigned)ROWB), "r"(fb)
                        : "memory");
                }
            }
        }
        return;
    }

    // ================= consumers (0..383): prep under flying loads =========
    BAR(0, NT);
    if (t < LW) s_bm[t] = 0u;
    BAR(1, NCONS);
    if (t < R_) {
        int v = remove_idx[b * R_ + t];
        if ((unsigned)v < 1536u) atomicOr(&s_bm[v >> 5], 1u << (v & 31));
    }
    BAR(1, NCONS);

    int keep = 0;
    if (t < G_) {
        const int* gi = patch_idx + (b * G_ + t) * K_;
        int cnt = 0;
#pragma unroll
        for (int k = 0; k < K_; k++) {
            int v = gi[k];
            bool valid = (v != -1);
            if (valid && (unsigned)v < 1536u)
                valid = ((s_bm[v >> 5] >> (v & 31)) & 1u) == 0u;
            cnt += valid ? 1 : 0;
        }
        s_cnt[t] = cnt;
        keep = (cnt > 0) ? 1 : 0;
    }
    const unsigned bmask = __ballot_sync(0xFFFFFFFFu, keep);
    const int w = t >> 5, lane = t & 31;
    if (lane == 0 && w < 5) s_kw[w] = bmask;
    BAR(1, NCONS);
    if (t < 5) s_wp[t] = __popc(s_kw[t]);
    BAR(1, NCONS);

    if (t < PPB) {
        int g = g0 + t;
        int nk = s_wp[0] + s_wp[1] + s_wp[2] + s_wp[3] + s_wp[4];
        int wi = g >> 5;
        int rk = __popc(s_kw[wi] & ((1u << (g & 31)) - 1u));
        for (int w2 = 0; w2 < wi; w2++) rk += s_wp[w2];
        int kp = (s_kw[wi] >> (g & 31)) & 1u;
        int dest = kp ? (MAXT - nk + rk) : (g - rk);   // permutation of 0..149
        s_dest[t] = dest;
        s_inv[t]  = kp ? 1.0f / (float)max(s_cnt[g], 1) : 0.0f;
        attn_out[b * MAXT + dest] = kp ? 1.0f : 0.0f;
    }
    BAR(1, NCONS);

    // ================= consume: 10 groups x 3 trios ========================
    float* osample = out + (size_t)b * MAXT * D_;
#pragma unroll 1
    for (int i = 0; i < PPB; i++) {
        float4 acc = make_float4(0.f, 0.f, 0.f, 0.f);
#pragma unroll 1
        for (int t3 = 0; t3 < 3; t3++) {
            int tr = i * 3 + t3;
            int s = tr & 1, u = tr >> 1;
            mbar_wait_acq(fullb0 + 8u * s, (unsigned)(u & 1));
            const float4* p = reinterpret_cast<const float4*>(s_slots + s * TRIOB);
#pragma unroll
            for (int r = 0; r < TRIOR; r++) {
                float4 v = p[r * (ROWB / 16) + t];
                acc.x += v.x; acc.y += v.y; acc.z += v.z; acc.w += v.w;
            }
            __syncwarp();
            if (lane == 0)
                asm volatile("mbarrier.arrive.shared.b64 _, [%0];"
                             :: "r"(emptyb0 + 8u * s) : "memory");
        }
        const float inv = s_inv[i];
        acc.x *= inv; acc.y *= inv; acc.z *= inv; acc.w *= inv;
        reinterpret_cast<float4*>(osample + (size_t)s_dest[i] * D_)[t] = acc;
    }
}

extern "C" void kernel_launch(void* const* d_in, const int* in_sizes, int n_in,
                              void* d_out, int out_size)
{
    const float* hidden    = (const float*)d_in[0];  // [B,S,D] f32
    // d_in[1] attention_mask, d_in[2] image_grid_thw: unused by the math
    const int* patch_range = (const int*)d_in[3];    // [B,2]
    const int* patch_idx   = (const int*)d_in[4];    // [B,G,K]
    const int* remove_idx  = (const int*)d_in[5];    // [B,R]

    float* out      = (float*)d_out;                 // [B,MAXT,D]
    float* attn_out = out + (size_t)B_ * MAXT * D_;  // [B,MAXT]

    dim3 grid(CHUNKS, B_);
    fused_pool_gc<<<grid, NT>>>(hidden, patch_range, patch_idx, remove_idx,
                                out, attn_out);
}